// round 11
// baseline (speedup 1.0000x reference)
#include <cuda_runtime.h>
#include <cuda_fp16.h>
#include <math.h>

// Problem constants
#define BATCH    4
#define HW_IN    (512 * 512)         // gaussians per batch (2^18)
#define W_OUT    1024
#define HW_OUT   (1024 * 1024)
#define N_GAUSS  (BATCH * HW_IN)     // 1,048,576
#define OUT_ELEMS (BATCH * 3 * HW_OUT)
#define N4_OUT   (OUT_ELEMS / 4)
#define NGRP     (OUT_ELEMS / 8)     // 8-pixel groups in final pass

// Border privatization (proven): ~73% of gaussians clamp to the border ring,
// f32 red.v4 into replicated compact scratch. Zero-invariant.
#define R_REP    16
#define BI_N     4096
__device__ float4 g_border[R_REP * BATCH * BI_N];          // 4 MB  (zero-invariant)
__device__ float4 g_bsum[BATCH * BI_N];                    // 256 KB (overwritten)

// Interior accumulator in FP16: 25 MB (vs 50 MB f32) so it stays L2-resident
// across replays together with the transient out writes (~108MB < 126MB L2).
// Zero-invariant: module load zeroes it; final re-zeros behind itself.
// Precision: f16 atomic accumulation adds ~1.4e-4 rms relative noise to
// interior pixels only (0..~7 contributions each); border stays f32. Global
// rel_err ~2e-4 << 1e-3 threshold.
__device__ __half g_hacc[OUT_ELEMS];                       // 25 MB

// ---------------------------------------------------------------------------
// Kernel 1: scatter. Border -> f32 red.v4 replicas. Interior -> f16 red adds.
// Framebuffer (d_out) untouched.
// ---------------------------------------------------------------------------
__global__ void gr_scatter_kernel(const float* __restrict__ uv,
                                  const float* __restrict__ pos) {
    int gid = blockIdx.x * blockDim.x + threadIdx.x;
    if (gid >= N_GAUSS) return;
    int b = gid >> 18;            // / HW_IN
    int n = gid & (HW_IN - 1);

    const float* uvb  = uv  + (size_t)b * 14 * HW_IN;
    const float* posb = pos + (size_t)b * 3 * HW_IN;

    float p0 = __ldcs(posb + n);
    float p1 = __ldcs(posb + HW_IN + n);
    float u0 = __ldcs(uvb + n);
    float u1 = __ldcs(uvb + HW_IN + n);
    float uo = __ldcs(uvb + 10 * HW_IN + n);
    float c0 = __ldcs(uvb + 11 * HW_IN + n);
    float c1 = __ldcs(uvb + 12 * HW_IN + n);
    float c2 = __ldcs(uvb + 13 * HW_IN + n);

    float x = p0 + u0;
    float y = p1 + u1;
    float o = 1.0f / (1.0f + __expf(-uo));
    float r  = c0 * o;
    float g  = c1 * o;
    float bl = c2 * o;

    // truncating cast then clamp (matches .astype(int32) + clip)
    int px = (int)((x + 1.0f) * 0.5f * (float)W_OUT);
    int py = (int)((y + 1.0f) * 0.5f * (float)W_OUT);
    px = min(max(px, 0), W_OUT - 1);
    py = min(max(py, 0), W_OUT - 1);

    bool border = (px == 0) | (px == W_OUT - 1) | (py == 0) | (py == W_OUT - 1);
    if (border) {
        // compact border index:
        //   py==0 -> px | py==1023 -> 1024+px | px==0 -> 2048+py | px==1023 -> 3072+py
        int bi = (py == 0)         ? px
               : (py == W_OUT - 1) ? (1024 + px)
               : (px == 0)         ? (2048 + py)
                                   : (3072 + py);
        int rep = gid & (R_REP - 1);   // lane-indexed: same-warp corners spread
        float* p = (float*)&g_border[(rep * BATCH + b) * BI_N + bi];
        asm volatile("red.global.add.v4.f32 [%0], {%1, %2, %3, %4};"
                     :: "l"(p), "f"(r), "f"(g), "f"(bl), "f"(0.0f)
                     : "memory");
    } else {
        size_t idx = (size_t)(b * 3) * HW_OUT + (size_t)py * W_OUT + px;
        atomicAdd(g_hacc + idx,              __float2half(r));
        atomicAdd(g_hacc + idx + HW_OUT,     __float2half(g));
        atomicAdd(g_hacc + idx + 2 * HW_OUT, __float2half(bl));
    }
}

// ---------------------------------------------------------------------------
// Kernel 2: collapse border replicas -> g_bsum, re-zero g_border (invariant).
// ---------------------------------------------------------------------------
__global__ void gr_repreduce_kernel() {
    int t = blockIdx.x * blockDim.x + threadIdx.x;   // [0, BATCH*BI_N)
    if (t >= BATCH * BI_N) return;
    float a0 = 0.f, a1 = 0.f, a2 = 0.f;
    float4 z = make_float4(0.f, 0.f, 0.f, 0.f);
    #pragma unroll
    for (int rp = 0; rp < R_REP; ++rp) {
        float4 v = g_border[rp * BATCH * BI_N + t];
        a0 += v.x; a1 += v.y; a2 += v.z;
        g_border[rp * BATCH * BI_N + t] = z;
    }
    g_bsum[t] = make_float4(a0, a1, a2, 0.f);
}

// ---------------------------------------------------------------------------
// Kernel 3: final. Each thread owns 8 pixels of one channel row:
// uint4-load 8 f16 accum values, re-zero them (invariant), add f32 border
// sums (border pixels receive ONLY border-path contributions; their f16
// slots are exactly zero), saturate, streaming-store 2 float4 to out.
// ---------------------------------------------------------------------------
__global__ void gr_final_kernel(float4* __restrict__ out) {
    int i = blockIdx.x * blockDim.x + threadIdx.x;
    if (i >= NGRP) return;

    int pc  = i >> 17;           // plane b*3+c (131072 groups per plane)
    int e   = i & 0x1FFFF;
    int row = e >> 7;            // 128 groups of 8 per row
    int g8  = e & 127;
    int b = pc / 3;
    int c = pc - 3 * b;
    int x0 = g8 << 3;

    size_t base = (size_t)pc * HW_OUT + (size_t)row * W_OUT + x0;
    uint4 hraw = *reinterpret_cast<const uint4*>(g_hacc + base);
    *reinterpret_cast<uint4*>(g_hacc + base) = make_uint4(0u, 0u, 0u, 0u);

    const __half2* hp = reinterpret_cast<const __half2*>(&hraw);
    float2 f0 = __half22float2(hp[0]);
    float2 f1 = __half22float2(hp[1]);
    float2 f2 = __half22float2(hp[2]);
    float2 f3 = __half22float2(hp[3]);
    float v[8] = { f0.x, f0.y, f1.x, f1.y, f2.x, f2.y, f3.x, f3.y };

    const float* gb = (const float*)(g_bsum + b * BI_N);   // [bi][4]
    if (row == 0) {
        #pragma unroll
        for (int k = 0; k < 8; ++k) v[k] += gb[(x0 + k) * 4 + c];
    } else if (row == W_OUT - 1) {
        #pragma unroll
        for (int k = 0; k < 8; ++k) v[k] += gb[(1024 + x0 + k) * 4 + c];
    } else {
        if (g8 == 0)   v[0] += gb[(2048 + row) * 4 + c];
        if (g8 == 127) v[7] += gb[(3072 + row) * 4 + c];
    }

    #pragma unroll
    for (int k = 0; k < 8; ++k) v[k] = __saturatef(v[k]);

    size_t o4 = base >> 2;
    __stcs(out + o4,     make_float4(v[0], v[1], v[2], v[3]));
    __stcs(out + o4 + 1, make_float4(v[4], v[5], v[6], v[7]));
}

// ---------------------------------------------------------------------------
extern "C" void kernel_launch(void* const* d_in, const int* in_sizes, int n_in,
                              void* d_out, int out_size) {
    const float* uv  = (const float*)d_in[0];   // [4,14,512,512]
    const float* pos = (const float*)d_in[1];   // [4,3,512,512]
    float* out = (float*)d_out;                 // [4,3,1024,1024]

    const int TPB = 256;

    gr_scatter_kernel<<<(N_GAUSS + TPB - 1) / TPB, TPB>>>(uv, pos);
    gr_repreduce_kernel<<<(BATCH * BI_N + TPB - 1) / TPB, TPB>>>();
    gr_final_kernel<<<(NGRP + TPB - 1) / TPB, TPB>>>((float4*)out);
}

// round 14
// speedup vs baseline: 1.4752x; 1.4752x over previous
#include <cuda_runtime.h>
#include <cuda_fp16.h>
#include <math.h>

// Problem constants
#define BATCH    4
#define HW_IN    (512 * 512)         // gaussians per batch (2^18)
#define W_OUT    1024
#define HW_OUT   (1024 * 1024)
#define N_GAUSS  (BATCH * HW_IN)     // 1,048,576
#define OUT_ELEMS (BATCH * 3 * HW_OUT)
#define NGRP     (OUT_ELEMS / 8)     // 8-pixel groups in final pass

// Border privatization (proven): ~73% of gaussians clamp to the border ring,
// f32 red.v4 into replicated compact scratch.
#define R_REP    16
#define BI_N     4096
__device__ float4 g_border[R_REP * BATCH * BI_N];          // 4 MB
__device__ float4 g_bsum[BATCH * BI_N];                    // 256 KB

// Interior accumulator in FP16 (validated R11: rel_err 1.5e-4 << 1e-3).
// EXPLICITLY zeroed each launch: the zero pass doubles as an L2 prefetch that
// installs the accumulator lines as dirty zeros right before the atomics hit
// them (R7/R9/R11 showed scatter atomics DRAM-miss without this).
__device__ __half g_hacc[OUT_ELEMS];                       // 25 MB

// Zeroing extents (uint4 = 16B granules)
#define NZ_HACC   (OUT_ELEMS * 2 / 16)            // 1,572,864
#define NZ_BORDER (R_REP * BATCH * BI_N)          //   262,144
#define NZ_TOTAL  (NZ_HACC + NZ_BORDER)           // 1,835,008

// ---------------------------------------------------------------------------
// Kernel 1: zero f16 accumulator + border scratch (29 MB, ~5.5us) — also the
// L2 warm-up for the scatter atomics.
// ---------------------------------------------------------------------------
__global__ void gr_zero_kernel() {
    int i = blockIdx.x * blockDim.x + threadIdx.x;
    uint4 z = make_uint4(0u, 0u, 0u, 0u);
    if (i < NZ_HACC) {
        reinterpret_cast<uint4*>(g_hacc)[i] = z;
    } else if (i < NZ_TOTAL) {
        reinterpret_cast<uint4*>(g_border)[i - NZ_HACC] = z;
    }
}

// ---------------------------------------------------------------------------
// Kernel 2: scatter. Border -> f32 red.v4 replicas (lane-spread). Interior ->
// 3 scalar f16 REDs into the warm accumulator. Inputs streamed with __ldcs
// so the 33 MB of read-once data doesn't evict the accumulators from L2.
// ---------------------------------------------------------------------------
__global__ void gr_scatter_kernel(const float* __restrict__ uv,
                                  const float* __restrict__ pos) {
    int gid = blockIdx.x * blockDim.x + threadIdx.x;
    if (gid >= N_GAUSS) return;
    int b = gid >> 18;            // / HW_IN
    int n = gid & (HW_IN - 1);

    const float* uvb  = uv  + (size_t)b * 14 * HW_IN;
    const float* posb = pos + (size_t)b * 3 * HW_IN;

    float p0 = __ldcs(posb + n);
    float p1 = __ldcs(posb + HW_IN + n);
    float u0 = __ldcs(uvb + n);
    float u1 = __ldcs(uvb + HW_IN + n);
    float uo = __ldcs(uvb + 10 * HW_IN + n);
    float c0 = __ldcs(uvb + 11 * HW_IN + n);
    float c1 = __ldcs(uvb + 12 * HW_IN + n);
    float c2 = __ldcs(uvb + 13 * HW_IN + n);

    float x = p0 + u0;
    float y = p1 + u1;
    float o = 1.0f / (1.0f + __expf(-uo));
    float r  = c0 * o;
    float g  = c1 * o;
    float bl = c2 * o;

    // truncating cast then clamp (matches .astype(int32) + clip)
    int px = (int)((x + 1.0f) * 0.5f * (float)W_OUT);
    int py = (int)((y + 1.0f) * 0.5f * (float)W_OUT);
    px = min(max(px, 0), W_OUT - 1);
    py = min(max(py, 0), W_OUT - 1);

    bool border = (px == 0) | (px == W_OUT - 1) | (py == 0) | (py == W_OUT - 1);
    if (border) {
        // compact border index:
        //   py==0 -> px | py==1023 -> 1024+px | px==0 -> 2048+py | px==1023 -> 3072+py
        int bi = (py == 0)         ? px
               : (py == W_OUT - 1) ? (1024 + px)
               : (px == 0)         ? (2048 + py)
                                   : (3072 + py);
        int rep = gid & (R_REP - 1);   // lane-indexed: same-warp corners spread
        float* p = (float*)&g_border[(rep * BATCH + b) * BI_N + bi];
        asm volatile("red.global.add.v4.f32 [%0], {%1, %2, %3, %4};"
                     :: "l"(p), "f"(r), "f"(g), "f"(bl), "f"(0.0f)
                     : "memory");
    } else {
        size_t idx = (size_t)(b * 3) * HW_OUT + (size_t)py * W_OUT + px;
        atomicAdd(g_hacc + idx,              __float2half(r));
        atomicAdd(g_hacc + idx + HW_OUT,     __float2half(g));
        atomicAdd(g_hacc + idx + 2 * HW_OUT, __float2half(bl));
    }
}

// ---------------------------------------------------------------------------
// Kernel 3: collapse border replicas -> g_bsum.
// ---------------------------------------------------------------------------
__global__ void gr_repreduce_kernel() {
    int t = blockIdx.x * blockDim.x + threadIdx.x;   // [0, BATCH*BI_N)
    if (t >= BATCH * BI_N) return;
    float a0 = 0.f, a1 = 0.f, a2 = 0.f;
    #pragma unroll
    for (int rp = 0; rp < R_REP; ++rp) {
        float4 v = g_border[rp * BATCH * BI_N + t];
        a0 += v.x; a1 += v.y; a2 += v.z;
    }
    g_bsum[t] = make_float4(a0, a1, a2, 0.f);
}

// ---------------------------------------------------------------------------
// Kernel 4: final. Each thread owns 8 pixels of one channel row: uint4-load
// 8 f16 accum values, add f32 border sums (border pixels' f16 slots are
// exactly zero — they only receive via the border path), saturate,
// streaming-store 2 float4 to out. No accumulator writes.
// ---------------------------------------------------------------------------
__global__ void gr_final_kernel(float4* __restrict__ out) {
    int i = blockIdx.x * blockDim.x + threadIdx.x;
    if (i >= NGRP) return;

    int pc  = i >> 17;           // plane b*3+c (131072 groups per plane)
    int e   = i & 0x1FFFF;
    int row = e >> 7;            // 128 groups of 8 per row
    int g8  = e & 127;
    int b = pc / 3;
    int c = pc - 3 * b;
    int x0 = g8 << 3;

    size_t base = (size_t)pc * HW_OUT + (size_t)row * W_OUT + x0;
    uint4 hraw = *reinterpret_cast<const uint4*>(g_hacc + base);

    const __half2* hp = reinterpret_cast<const __half2*>(&hraw);
    float2 f0 = __half22float2(hp[0]);
    float2 f1 = __half22float2(hp[1]);
    float2 f2 = __half22float2(hp[2]);
    float2 f3 = __half22float2(hp[3]);
    float v[8] = { f0.x, f0.y, f1.x, f1.y, f2.x, f2.y, f3.x, f3.y };

    const float* gb = (const float*)(g_bsum + b * BI_N);   // [bi][4]
    if (row == 0) {
        #pragma unroll
        for (int k = 0; k < 8; ++k) v[k] += gb[(x0 + k) * 4 + c];
    } else if (row == W_OUT - 1) {
        #pragma unroll
        for (int k = 0; k < 8; ++k) v[k] += gb[(1024 + x0 + k) * 4 + c];
    } else {
        if (g8 == 0)   v[0] += gb[(2048 + row) * 4 + c];
        if (g8 == 127) v[7] += gb[(3072 + row) * 4 + c];
    }

    #pragma unroll
    for (int k = 0; k < 8; ++k) v[k] = __saturatef(v[k]);

    size_t o4 = base >> 2;
    __stcs(out + o4,     make_float4(v[0], v[1], v[2], v[3]));
    __stcs(out + o4 + 1, make_float4(v[4], v[5], v[6], v[7]));
}

// ---------------------------------------------------------------------------
extern "C" void kernel_launch(void* const* d_in, const int* in_sizes, int n_in,
                              void* d_out, int out_size) {
    const float* uv  = (const float*)d_in[0];   // [4,14,512,512]
    const float* pos = (const float*)d_in[1];   // [4,3,512,512]
    float* out = (float*)d_out;                 // [4,3,1024,1024]

    const int TPB = 256;

    gr_zero_kernel<<<(NZ_TOTAL + TPB - 1) / TPB, TPB>>>();
    gr_scatter_kernel<<<(N_GAUSS + TPB - 1) / TPB, TPB>>>(uv, pos);
    gr_repreduce_kernel<<<(BATCH * BI_N + TPB - 1) / TPB, TPB>>>();
    gr_final_kernel<<<(NGRP + TPB - 1) / TPB, TPB>>>((float4*)out);
}

// round 15
// speedup vs baseline: 2.1229x; 1.4390x over previous
#include <cuda_runtime.h>
#include <cuda_fp16.h>
#include <math.h>

// Problem constants
#define BATCH    4
#define HW_IN    (512 * 512)         // gaussians per batch (2^18)
#define W_OUT    1024
#define HW_OUT   (1024 * 1024)
#define N_GAUSS  (BATCH * HW_IN)     // 1,048,576
#define OUT_ELEMS (BATCH * 3 * HW_OUT)
#define N_PIX    (BATCH * HW_OUT)    // 4,194,304
#define NGRP4    (N_PIX / 4)         // final pass: 4 pixels / thread

// Border privatization (proven): ~73% of gaussians clamp to the border ring,
// f32 red.v4 into replicated compact scratch, lane-spread replicas.
#define R_REP    16
#define BI_N     4096
__device__ float4 g_border[R_REP * BATCH * BI_N];          // 4 MB
__device__ float4 g_bsum[BATCH * BI_N];                    // 256 KB

// Interior accumulator: pixel-interleaved f16x4 (r,g,b,pad) = 8 B/pixel.
// ONE red.global.add.noftz.v2.f16x2 per interior gaussian (1 op, 1 line)
// vs 3 scalar REDs/3 lines in the planar layouts. 32 MB, L2-resident.
// f16 accumulation precision validated in R11/R14 (rel_err 1.5e-4 << 1e-3).
__device__ uint2 g_pacc[N_PIX];                            // 32 MB

// Zeroing extents (uint4 granules): 32 MB pacc + 4 MB border
#define NZ_PACC   (N_PIX / 2)                     // 2,097,152
#define NZ_BORDER (R_REP * BATCH * BI_N)          //   262,144
#define NZ_TOTAL  (NZ_PACC + NZ_BORDER)

// ---------------------------------------------------------------------------
// Kernel 1: zero accumulators (36 MB) — doubles as the L2 prefetch that keeps
// the scatter atomics out of DRAM (proven necessary in R7/R11).
// ---------------------------------------------------------------------------
__global__ void gr_zero_kernel() {
    int i = blockIdx.x * blockDim.x + threadIdx.x;
    uint4 z = make_uint4(0u, 0u, 0u, 0u);
    if (i < NZ_PACC) {
        reinterpret_cast<uint4*>(g_pacc)[i] = z;
    } else if (i < NZ_TOTAL) {
        reinterpret_cast<uint4*>(g_border)[i - NZ_PACC] = z;
    }
}

// ---------------------------------------------------------------------------
// Kernel 2: scatter. Border -> f32 red.v4 replicas. Interior -> single
// vector f16x4 RED into the interleaved accumulator.
// ---------------------------------------------------------------------------
__global__ void gr_scatter_kernel(const float* __restrict__ uv,
                                  const float* __restrict__ pos) {
    int gid = blockIdx.x * blockDim.x + threadIdx.x;
    if (gid >= N_GAUSS) return;
    int b = gid >> 18;            // / HW_IN
    int n = gid & (HW_IN - 1);

    const float* uvb  = uv  + (size_t)b * 14 * HW_IN;
    const float* posb = pos + (size_t)b * 3 * HW_IN;

    float p0 = __ldcs(posb + n);
    float p1 = __ldcs(posb + HW_IN + n);
    float u0 = __ldcs(uvb + n);
    float u1 = __ldcs(uvb + HW_IN + n);
    float uo = __ldcs(uvb + 10 * HW_IN + n);
    float c0 = __ldcs(uvb + 11 * HW_IN + n);
    float c1 = __ldcs(uvb + 12 * HW_IN + n);
    float c2 = __ldcs(uvb + 13 * HW_IN + n);

    float x = p0 + u0;
    float y = p1 + u1;
    float o = 1.0f / (1.0f + __expf(-uo));
    float r  = c0 * o;
    float g  = c1 * o;
    float bl = c2 * o;

    // truncating cast then clamp (matches .astype(int32) + clip)
    int px = (int)((x + 1.0f) * 0.5f * (float)W_OUT);
    int py = (int)((y + 1.0f) * 0.5f * (float)W_OUT);
    px = min(max(px, 0), W_OUT - 1);
    py = min(max(py, 0), W_OUT - 1);

    bool border = (px == 0) | (px == W_OUT - 1) | (py == 0) | (py == W_OUT - 1);
    if (border) {
        // compact border index:
        //   py==0 -> px | py==1023 -> 1024+px | px==0 -> 2048+py | px==1023 -> 3072+py
        int bi = (py == 0)         ? px
               : (py == W_OUT - 1) ? (1024 + px)
               : (px == 0)         ? (2048 + py)
                                   : (3072 + py);
        int rep = gid & (R_REP - 1);   // lane-indexed: same-warp corners spread
        float* p = (float*)&g_border[(rep * BATCH + b) * BI_N + bi];
        asm volatile("red.global.add.v4.f32 [%0], {%1, %2, %3, %4};"
                     :: "l"(p), "f"(r), "f"(g), "f"(bl), "f"(0.0f)
                     : "memory");
    } else {
        size_t idx = (size_t)b * HW_OUT + (size_t)py * W_OUT + px;
        __half2 hrg = __floats2half2_rn(r, g);
        __half2 hb  = __floats2half2_rn(bl, 0.0f);
        unsigned urg = *reinterpret_cast<unsigned*>(&hrg);
        unsigned ub  = *reinterpret_cast<unsigned*>(&hb);
        asm volatile("red.global.add.noftz.v2.f16x2 [%0], {%1, %2};"
                     :: "l"(g_pacc + idx), "r"(urg), "r"(ub)
                     : "memory");
    }
}

// ---------------------------------------------------------------------------
// Kernel 3: collapse border replicas -> g_bsum.
// ---------------------------------------------------------------------------
__global__ void gr_repreduce_kernel() {
    int t = blockIdx.x * blockDim.x + threadIdx.x;   // [0, BATCH*BI_N)
    if (t >= BATCH * BI_N) return;
    float a0 = 0.f, a1 = 0.f, a2 = 0.f;
    #pragma unroll
    for (int rp = 0; rp < R_REP; ++rp) {
        float4 v = g_border[rp * BATCH * BI_N + t];
        a0 += v.x; a1 += v.y; a2 += v.z;
    }
    g_bsum[t] = make_float4(a0, a1, a2, 0.f);
}

// ---------------------------------------------------------------------------
// Kernel 4: final. Each thread owns 4 consecutive pixels: two uint4 loads of
// interleaved f16x4, register transpose to planar, add f32 border sums
// (border pixels' interleaved slots are exactly zero — they only receive via
// the border path), saturate, 3 streaming float4 stores (one per channel).
// ---------------------------------------------------------------------------
__global__ void gr_final_kernel(float4* __restrict__ out) {
    int i = blockIdx.x * blockDim.x + threadIdx.x;
    if (i >= NGRP4) return;

    int b   = i >> 18;           // 262144 groups per batch
    int e   = i & 0x3FFFF;
    int row = e >> 8;            // 256 groups of 4 per row
    int g4  = e & 255;
    int x0  = g4 << 2;

    size_t pbase = (size_t)b * HW_OUT + ((size_t)row << 10) + x0;
    const uint4* pp = reinterpret_cast<const uint4*>(g_pacc + pbase);
    uint4 q0 = pp[0];            // pixels 0,1: (rg, b_), (rg, b_)
    uint4 q1 = pp[1];            // pixels 2,3

    float r[4], g[4], bl[4];
    {
        float2 t;
        t = __half22float2(*reinterpret_cast<__half2*>(&q0.x)); r[0]=t.x; g[0]=t.y;
        t = __half22float2(*reinterpret_cast<__half2*>(&q0.y)); bl[0]=t.x;
        t = __half22float2(*reinterpret_cast<__half2*>(&q0.z)); r[1]=t.x; g[1]=t.y;
        t = __half22float2(*reinterpret_cast<__half2*>(&q0.w)); bl[1]=t.x;
        t = __half22float2(*reinterpret_cast<__half2*>(&q1.x)); r[2]=t.x; g[2]=t.y;
        t = __half22float2(*reinterpret_cast<__half2*>(&q1.y)); bl[2]=t.x;
        t = __half22float2(*reinterpret_cast<__half2*>(&q1.z)); r[3]=t.x; g[3]=t.y;
        t = __half22float2(*reinterpret_cast<__half2*>(&q1.w)); bl[3]=t.x;
    }

    const float4* gb = g_bsum + b * BI_N;
    if (row == 0) {
        #pragma unroll
        for (int k = 0; k < 4; ++k) {
            float4 s = gb[x0 + k];
            r[k] += s.x; g[k] += s.y; bl[k] += s.z;
        }
    } else if (row == W_OUT - 1) {
        #pragma unroll
        for (int k = 0; k < 4; ++k) {
            float4 s = gb[1024 + x0 + k];
            r[k] += s.x; g[k] += s.y; bl[k] += s.z;
        }
    } else {
        if (g4 == 0)   { float4 s = gb[2048 + row]; r[0] += s.x; g[0] += s.y; bl[0] += s.z; }
        if (g4 == 255) { float4 s = gb[3072 + row]; r[3] += s.x; g[3] += s.y; bl[3] += s.z; }
    }

    #pragma unroll
    for (int k = 0; k < 4; ++k) {
        r[k]  = __saturatef(r[k]);
        g[k]  = __saturatef(g[k]);
        bl[k] = __saturatef(bl[k]);
    }

    size_t obase = (((size_t)(b * 3) * HW_OUT) + ((size_t)row << 10) + x0) >> 2;
    const size_t plane4 = HW_OUT >> 2;
    __stcs(out + obase,              make_float4(r[0],  r[1],  r[2],  r[3]));
    __stcs(out + obase + plane4,     make_float4(g[0],  g[1],  g[2],  g[3]));
    __stcs(out + obase + 2 * plane4, make_float4(bl[0], bl[1], bl[2], bl[3]));
}

// ---------------------------------------------------------------------------
extern "C" void kernel_launch(void* const* d_in, const int* in_sizes, int n_in,
                              void* d_out, int out_size) {
    const float* uv  = (const float*)d_in[0];   // [4,14,512,512]
    const float* pos = (const float*)d_in[1];   // [4,3,512,512]
    float* out = (float*)d_out;                 // [4,3,1024,1024]

    const int TPB = 256;

    gr_zero_kernel<<<(NZ_TOTAL + TPB - 1) / TPB, TPB>>>();
    gr_scatter_kernel<<<(N_GAUSS + TPB - 1) / TPB, TPB>>>(uv, pos);
    gr_repreduce_kernel<<<(BATCH * BI_N + TPB - 1) / TPB, TPB>>>();
    gr_final_kernel<<<(NGRP4 + TPB - 1) / TPB, TPB>>>((float4*)out);
}